// round 2
// baseline (speedup 1.0000x reference)
#include <cuda_runtime.h>
#include <cstdint>

#define BB 4
#define CC 192
#define NN 8192
#define KK 16
#define COUT 192
#define TWOC 384
#define TILE_N 64
#define SYS 385            // sy row stride in floats (odd -> avoids bad bank strides)
#define THREADS 256

#define SY_BYTES   (TILE_N * SYS * 4)            // 98560
#define WSD_OFF    SY_BYTES
#define WSD_BYTES  (COUT * 33 * 8)               // 50688 (duplicated W pairs)
#define IDX_OFF    (WSD_OFF + WSD_BYTES)         // 149248
#define SMEM_TOTAL (IDX_OFF + 2 * TILE_N * KK * 4)  // 157440

typedef unsigned long long ull;

// Scratch: x transposed to [B, N, C] so a gathered node-column is 768B contiguous.
__device__ float g_xt[(size_t)BB * NN * CC];

// ---------------------------------------------------------------------------
// Kernel 1: transpose x [B, C, N] -> g_xt [B, N, C]
// ---------------------------------------------------------------------------
__global__ void transpose_kernel(const float* __restrict__ x) {
    __shared__ float tile[32][33];
    int b  = blockIdx.z;
    int n0 = blockIdx.x * 32;
    int c0 = blockIdx.y * 32;
    int tx = threadIdx.x, ty = threadIdx.y;
    const float* in  = x   + (size_t)b * CC * NN;
    float*      outp = g_xt + (size_t)b * NN * CC;
#pragma unroll
    for (int i = 0; i < 32; i += 8)
        tile[ty + i][tx] = in[(size_t)(c0 + ty + i) * NN + n0 + tx];
    __syncthreads();
#pragma unroll
    for (int i = 0; i < 32; i += 8)
        outp[(size_t)(n0 + ty + i) * CC + c0 + tx] = tile[tx][ty + i];
}

// ---------------------------------------------------------------------------
// Kernel 2: fused gather + max-relative + concat + 1x1 conv (GEMM) + bias + relu
// Block: 256 threads, one (batch, 64-node tile).
// ---------------------------------------------------------------------------
__global__ __launch_bounds__(THREADS, 1)
void fused_kernel(const int* __restrict__ edge, const float* __restrict__ W,
                  const float* __restrict__ bias, float* __restrict__ out) {
    extern __shared__ char smem[];
    float*  sy  = (float*)smem;                 // y tile: [64 nodes][385] (c in 0..383)
    float2* wsd = (float2*)(smem + WSD_OFF);    // W chunk, duplicated: [o][33] of {w,w}
    ull*    wsq = (ull*)wsd;
    float*  stg = (float*)wsd;                  // epilogue staging (aliases wsd)
    int*    sj  = (int*)(smem + IDX_OFF);       // edge_index[0] (neighbors j)
    int*    si  = sj + TILE_N * KK;             // edge_index[1] (centers i)

    const int tid = threadIdx.x;
    const int bid = blockIdx.x;
    const int b   = bid >> 7;                   // 128 tiles per batch
    const int n0  = (bid & 127) * TILE_N;

    // ---- load edge indices for this tile (coalesced) ----
    {
        const int* ej = edge + ((size_t)b * NN + n0) * KK;
        const int* ei = edge + ((size_t)(BB + b) * NN + n0) * KK;
        for (int t = tid; t < TILE_N * KK; t += THREADS) {
            sj[t] = ej[t];
            si[t] = ei[t];
        }
    }
    __syncthreads();

    // ---- gather + max-relative; build y tile in smem ----
    // warp w handles nodes w, w+8, ...; lane covers channels {2l, 2l+1} + {64,128} chunks
    const float* bx  = g_xt + (size_t)b * NN * CC;
    const int wid  = tid >> 5;
    const int lane = tid & 31;
    const int cb   = lane * 2;
    for (int nn = wid; nn < TILE_N; nn += 8) {
        const float* pc = bx + (size_t)(n0 + nn) * CC + cb;
        float2 v0 = *(const float2*)(pc);
        float2 v1 = *(const float2*)(pc + 64);
        float2 v2 = *(const float2*)(pc + 128);
        float2 r0 = make_float2(-3.0e38f, -3.0e38f), r1 = r0, r2 = r0;
        const int* sjn = sj + nn * KK;
        const int* sin = si + nn * KK;
#pragma unroll 4
        for (int k = 0; k < KK; k++) {
            const float* pj = bx + (size_t)sjn[k] * CC + cb;
            const float* pi = bx + (size_t)sin[k] * CC + cb;
            float2 a0 = *(const float2*)(pj);       float2 c0v = *(const float2*)(pi);
            float2 a1 = *(const float2*)(pj + 64);  float2 c1v = *(const float2*)(pi + 64);
            float2 a2 = *(const float2*)(pj + 128); float2 c2v = *(const float2*)(pi + 128);
            r0.x = fmaxf(r0.x, a0.x - c0v.x); r0.y = fmaxf(r0.y, a0.y - c0v.y);
            r1.x = fmaxf(r1.x, a1.x - c1v.x); r1.y = fmaxf(r1.y, a1.y - c1v.y);
            r2.x = fmaxf(r2.x, a2.x - c2v.x); r2.y = fmaxf(r2.y, a2.y - c2v.y);
        }
        float* row = sy + nn * SYS;
        row[cb]            = v0.x; row[cb + 1]        = v0.y;
        row[cb + 64]       = v1.x; row[cb + 65]       = v1.y;
        row[cb + 128]      = v2.x; row[cb + 129]      = v2.y;
        row[CC + cb]       = r0.x; row[CC + cb + 1]   = r0.y;
        row[CC + cb + 64]  = r1.x; row[CC + cb + 65]  = r1.y;
        row[CC + cb + 128] = r2.x; row[CC + cb + 129] = r2.y;
    }

    // ---- GEMM: out[o][n] = relu(sum_c W[o][c] * y[c][n] + b[o]) ----
    // thread (oi, ni): oi = tid>>3 (32 groups x 6 outputs), ni = tid&7 (8 groups x 8 nodes)
    const int oi = tid >> 3;
    const int ni = tid & 7;

    float bv[6];
#pragma unroll
    for (int m = 0; m < 6; m++) bv[m] = bias[oi * 6 + m];

    ull acc[6][4];
#pragma unroll
    for (int m = 0; m < 6; m++)
#pragma unroll
        for (int p = 0; p < 4; p++) acc[m][p] = 0ULL;

    const ull*   wp = wsq + oi * 6 * 33;
    const float* yp = sy + ni * 8 * SYS;

    __syncthreads();   // y tile complete before GEMM reads

    for (int cc = 0; cc < TWOC / 32; cc++) {
        // stage W chunk [192 o][32 c], each value duplicated into a 64-bit pair
        const float* wsrc = W + cc * 32;
        for (int t = tid; t < COUT * 32; t += THREADS) {
            int o = t >> 5, kk = t & 31;
            float v = wsrc[(size_t)o * TWOC + kk];
            wsd[o * 33 + kk] = make_float2(v, v);
        }
        __syncthreads();

        const float* ypc = yp + cc * 32;
#pragma unroll 4
        for (int kk = 0; kk < 32; kk++) {
            ull w[6];
#pragma unroll
            for (int m = 0; m < 6; m++) w[m] = wp[m * 33 + kk];
            float yv[8];
#pragma unroll
            for (int t = 0; t < 8; t++) yv[t] = ypc[t * SYS + kk];
            ull y2[4];
#pragma unroll
            for (int p = 0; p < 4; p++)
                asm("mov.b64 %0, {%1, %2};" : "=l"(y2[p]) : "f"(yv[2 * p]), "f"(yv[2 * p + 1]));
#pragma unroll
            for (int m = 0; m < 6; m++)
#pragma unroll
                for (int p = 0; p < 4; p++)
                    asm("fma.rn.f32x2 %0, %1, %2, %3;"
                        : "=l"(acc[m][p])
                        : "l"(w[m]), "l"(y2[p]), "l"(acc[m][p]));
        }
        __syncthreads();   // done reading this W chunk
    }

    // ---- epilogue: bias + relu, restage through smem for coalesced stores ----
    const size_t outbase = (size_t)b * COUT * NN + n0;
#pragma unroll 1
    for (int m = 0; m < 6; m++) {
        __syncthreads();
#pragma unroll
        for (int p = 0; p < 4; p++) {
            float lo, hi;
            asm("mov.b64 {%0, %1}, %2;" : "=f"(lo), "=f"(hi) : "l"(acc[m][p]));
            lo = fmaxf(lo + bv[m], 0.0f);
            hi = fmaxf(hi + bv[m], 0.0f);
            stg[oi * 68 + ni * 8 + 2 * p]     = lo;
            stg[oi * 68 + ni * 8 + 2 * p + 1] = hi;
        }
        __syncthreads();
        // 32 rows (one per oi) x 64 nodes; each thread stores 8 contiguous floats
        int r   = tid >> 3;
        int col = (tid & 7) * 8;
        const float4* s4 = (const float4*)(stg + r * 68 + col);
        float4 q0 = s4[0], q1 = s4[1];
        float* op = out + outbase + (size_t)(r * 6 + m) * NN + col;
        *(float4*)(op)     = q0;
        *(float4*)(op + 4) = q1;
    }
}

// ---------------------------------------------------------------------------
// Launch
// ---------------------------------------------------------------------------
extern "C" void kernel_launch(void* const* d_in, const int* in_sizes, int n_in,
                              void* d_out, int out_size) {
    const float* x    = (const float*)d_in[0];
    // d_in[1] = x_0 (unused by forward)
    const int*   edge = (const int*)d_in[2];
    const float* W    = (const float*)d_in[3];
    const float* bias = (const float*)d_in[4];
    float*       out  = (float*)d_out;

    cudaFuncSetAttribute(fused_kernel, cudaFuncAttributeMaxDynamicSharedMemorySize,
                         SMEM_TOTAL);

    transpose_kernel<<<dim3(NN / 32, CC / 32, BB), dim3(32, 8)>>>(x);
    fused_kernel<<<BB * (NN / TILE_N), THREADS, SMEM_TOTAL>>>(edge, W, bias, out);
}